// round 1
// baseline (speedup 1.0000x reference)
#include <cuda_runtime.h>
#include <cstdint>

#define BB   2
#define SS   2048
#define DD   1024
#define HQ   16
#define HKV  8
#define HD   128
#define NTOK (BB*SS)     /* 4096 */
#define NBH  (BB*HQ)     /* 32   */

// ---------------- device scratch (static globals; no runtime allocation) ----
__device__ float g_qlin[(size_t)NTOK * HQ  * HD];   // [tok][2048]
__device__ float g_klin[(size_t)NTOK * HKV * HD];   // [tok][1024]
__device__ float g_vlin[(size_t)NTOK * HKV * HD];   // [tok][1024]
__device__ float g_q  [(size_t)BB * HQ  * SS * HD]; // [b][h][s][d]
__device__ float g_k  [(size_t)BB * HKV * SS * HD];
__device__ float g_v  [(size_t)BB * HKV * SS * HD];
__device__ float g_o  [(size_t)NTOK * HQ * HD];     // [b][s][h*128+d]
__device__ float g_wfall[(size_t)BB * HQ * SS * SS]; // fallback weights scratch

// =================== generic NT GEMM: C[M,N] = A[M,K] * B[N,K]^T ============
// Grid: (N/128, M/128), 256 threads. All dims multiples of 128, K mult of 8.
__global__ void gemm_nt_kernel(const float* __restrict__ A,
                               const float* __restrict__ Bm,
                               float* __restrict__ C,
                               int K, int lda, int ldb, int ldc)
{
    __shared__ float As[8][128];
    __shared__ float Bs[8][128];
    const int m0 = blockIdx.y * 128, n0 = blockIdx.x * 128;
    const int t  = threadIdx.x;
    const int ar = t >> 1, ac = (t & 1) * 4;
    const int tx = t & 15, ty = t >> 4;

    float acc[8][8];
#pragma unroll
    for (int i = 0; i < 8; i++)
#pragma unroll
        for (int j = 0; j < 8; j++) acc[i][j] = 0.f;

    const float* Ap = A  + (size_t)(m0 + ar) * lda + ac;
    const float* Bp = Bm + (size_t)(n0 + ar) * ldb + ac;

    for (int k0 = 0; k0 < K; k0 += 8) {
        float4 av = *(const float4*)(Ap + k0);
        float4 bv = *(const float4*)(Bp + k0);
        __syncthreads();
        As[ac + 0][ar] = av.x; As[ac + 1][ar] = av.y;
        As[ac + 2][ar] = av.z; As[ac + 3][ar] = av.w;
        Bs[ac + 0][ar] = bv.x; Bs[ac + 1][ar] = bv.y;
        Bs[ac + 2][ar] = bv.z; Bs[ac + 3][ar] = bv.w;
        __syncthreads();
#pragma unroll
        for (int k = 0; k < 8; k++) {
            float a[8], b[8];
            *(float4*)(a)     = *(const float4*)&As[k][ty * 4];
            *(float4*)(a + 4) = *(const float4*)&As[k][64 + ty * 4];
            *(float4*)(b)     = *(const float4*)&Bs[k][tx * 4];
            *(float4*)(b + 4) = *(const float4*)&Bs[k][64 + tx * 4];
#pragma unroll
            for (int i = 0; i < 8; i++)
#pragma unroll
                for (int j = 0; j < 8; j++) acc[i][j] += a[i] * b[j];
        }
    }
#pragma unroll
    for (int i = 0; i < 8; i++) {
        int m = m0 + ((i < 4) ? (ty * 4 + i) : (64 + ty * 4 + (i - 4)));
        float4 o0 = make_float4(acc[i][0], acc[i][1], acc[i][2], acc[i][3]);
        float4 o1 = make_float4(acc[i][4], acc[i][5], acc[i][6], acc[i][7]);
        *(float4*)&C[(size_t)m * ldc + n0 + tx * 4]      = o0;
        *(float4*)&C[(size_t)m * ldc + n0 + 64 + tx * 4] = o1;
    }
}

// ======== RMSNorm + RoPE (+ V relayout). Grid (NTOK, 24), 128 threads ======
__global__ void rmsrope_kernel(const float* __restrict__ qlin,
                               const float* __restrict__ klin,
                               const float* __restrict__ vlin,
                               const float* __restrict__ cosb,
                               const float* __restrict__ sinb,
                               const float* __restrict__ qw,
                               const float* __restrict__ kw,
                               float* __restrict__ qout,
                               float* __restrict__ kout,
                               float* __restrict__ vout)
{
    const int token = blockIdx.x;
    const int y     = blockIdx.y;
    const int i     = threadIdx.x;
    const int b = token >> 11, s = token & (SS - 1);
    __shared__ float sh[128];
    __shared__ float red[4];

    float c  = cosb[(size_t)token * HD + i];
    float sn = sinb[(size_t)token * HD + i];
    float x, w;
    float* outp;
    if (y < HQ) {
        x = qlin[(size_t)token * (HQ * HD) + y * HD + i];
        w = qw[i];
        outp = qout + (((size_t)(b * HQ + y)) * SS + s) * HD;
    } else {
        int h = y - HQ;
        x = klin[(size_t)token * (HKV * HD) + h * HD + i];
        w = kw[i];
        outp = kout + (((size_t)(b * HKV + h)) * SS + s) * HD;
        vout[(((size_t)(b * HKV + h)) * SS + s) * HD + i] =
            vlin[(size_t)token * (HKV * HD) + h * HD + i];
    }
    float ss = x * x;
#pragma unroll
    for (int off = 16; off; off >>= 1) ss += __shfl_xor_sync(0xffffffffu, ss, off);
    const int lane = i & 31, wid = i >> 5;
    if (lane == 0) red[wid] = ss;
    __syncthreads();
    ss = red[0] + red[1] + red[2] + red[3];
    float inv = rsqrtf(ss * (1.f / HD) + 1e-6f);
    float xn  = x * inv * w;
    sh[i] = xn;
    __syncthreads();
    float rot = (i < 64) ? -sh[i + 64] : sh[i - 64];
    outp[i] = xn * c + rot * sn;
}

// ====== scores: W[z] = scale * Q[z] @ K[kv(z)]^T, causal block-skip =========
// Grid (16,16,32), 256 threads. Upper-triangular 128x128 blocks skipped.
__global__ void scores_kernel(const float* __restrict__ Q,
                              const float* __restrict__ Kk,
                              float* __restrict__ W)
{
    const int bxv = blockIdx.x, byv = blockIdx.y, z = blockIdx.z;
    if (bxv > byv) return;
    const int kvz = (z >> 4) * HKV + ((z & 15) >> 1);
    const float* A  = Q  + (size_t)z   * SS * HD;
    const float* Bm = Kk + (size_t)kvz * SS * HD;
    float*       C  = W  + (size_t)z   * SS * SS;

    __shared__ float As[8][128];
    __shared__ float Bs[8][128];
    const int m0 = byv * 128, n0 = bxv * 128;
    const int t  = threadIdx.x;
    const int ar = t >> 1, ac = (t & 1) * 4;
    const int tx = t & 15, ty = t >> 4;

    float acc[8][8];
#pragma unroll
    for (int i = 0; i < 8; i++)
#pragma unroll
        for (int j = 0; j < 8; j++) acc[i][j] = 0.f;

    const float* Ap = A  + (size_t)(m0 + ar) * HD + ac;
    const float* Bp = Bm + (size_t)(n0 + ar) * HD + ac;

    for (int k0 = 0; k0 < HD; k0 += 8) {
        float4 av = *(const float4*)(Ap + k0);
        float4 bv = *(const float4*)(Bp + k0);
        __syncthreads();
        As[ac + 0][ar] = av.x; As[ac + 1][ar] = av.y;
        As[ac + 2][ar] = av.z; As[ac + 3][ar] = av.w;
        Bs[ac + 0][ar] = bv.x; Bs[ac + 1][ar] = bv.y;
        Bs[ac + 2][ar] = bv.z; Bs[ac + 3][ar] = bv.w;
        __syncthreads();
#pragma unroll
        for (int k = 0; k < 8; k++) {
            float a[8], b[8];
            *(float4*)(a)     = *(const float4*)&As[k][ty * 4];
            *(float4*)(a + 4) = *(const float4*)&As[k][64 + ty * 4];
            *(float4*)(b)     = *(const float4*)&Bs[k][tx * 4];
            *(float4*)(b + 4) = *(const float4*)&Bs[k][64 + tx * 4];
#pragma unroll
            for (int i = 0; i < 8; i++)
#pragma unroll
                for (int j = 0; j < 8; j++) acc[i][j] += a[i] * b[j];
        }
    }
    const float scale = 0.08838834764831845f;  // 128^-0.5
#pragma unroll
    for (int i = 0; i < 8; i++) {
        int m = m0 + ((i < 4) ? (ty * 4 + i) : (64 + ty * 4 + (i - 4)));
        float4 o0 = make_float4(acc[i][0]*scale, acc[i][1]*scale, acc[i][2]*scale, acc[i][3]*scale);
        float4 o1 = make_float4(acc[i][4]*scale, acc[i][5]*scale, acc[i][6]*scale, acc[i][7]*scale);
        *(float4*)&C[(size_t)m * SS + n0 + tx * 4]      = o0;
        *(float4*)&C[(size_t)m * SS + n0 + 64 + tx * 4] = o1;
    }
}

// ======= in-place causal softmax over rows of W. Grid B*HQ*SS, 256 thr =====
__global__ void softmax_kernel(float* __restrict__ W)
{
    const size_t row = blockIdx.x;
    const int iq = (int)(row & (SS - 1));
    float* p = W + row * SS;
    const int L = iq + 1;
    const int t = threadIdx.x;
    __shared__ float red[8];

    float m = -3.4e38f;
    for (int j = t; j < L; j += 256) m = fmaxf(m, p[j]);
#pragma unroll
    for (int off = 16; off; off >>= 1) m = fmaxf(m, __shfl_xor_sync(0xffffffffu, m, off));
    if ((t & 31) == 0) red[t >> 5] = m;
    __syncthreads();
    m = red[0];
#pragma unroll
    for (int wq = 1; wq < 8; wq++) m = fmaxf(m, red[wq]);
    __syncthreads();

    float ssum = 0.f;
    for (int j = t; j < L; j += 256) ssum += expf(p[j] - m);
#pragma unroll
    for (int off = 16; off; off >>= 1) ssum += __shfl_xor_sync(0xffffffffu, ssum, off);
    if ((t & 31) == 0) red[t >> 5] = ssum;
    __syncthreads();
    ssum = red[0] + red[1] + red[2] + red[3] + red[4] + red[5] + red[6] + red[7];
    const float inv = 1.f / ssum;

    for (int j = t; j < SS; j += 256) {
        float val = (j < L) ? expf(p[j] - m) * inv : 0.f;
        p[j] = val;
    }
}

// ======= AV (NN GEMM): O[z] = W[z] @ V[kv(z)], causal K bound ===============
// Grid (1,16,32), 256 threads.
__global__ void av_kernel(const float* __restrict__ W,
                          const float* __restrict__ V,
                          float* __restrict__ O)
{
    const int byv = blockIdx.y, z = blockIdx.z;
    const int kvz = (z >> 4) * HKV + ((z & 15) >> 1);
    const float* A  = W + (size_t)z   * SS * SS;   // lda = SS
    const float* Bv = V + (size_t)kvz * SS * HD;   // [k][n], ldb = HD
    float*       C  = O + (size_t)(z >> 4) * SS * (HQ * HD) + (z & 15) * HD; // ldc = 2048

    __shared__ float As[8][128];
    __shared__ float Bs[8][128];
    const int t  = threadIdx.x;
    const int ar = t >> 1,  ac = (t & 1) * 4;
    const int br = t >> 5,  bc = (t & 31) * 4;
    const int tx = t & 15,  ty = t >> 4;
    const int m0 = byv * 128;
    const int Kend = m0 + 128;   // causal: weights are 0 for k > row

    float acc[8][8];
#pragma unroll
    for (int i = 0; i < 8; i++)
#pragma unroll
        for (int j = 0; j < 8; j++) acc[i][j] = 0.f;

    const float* Ap = A + (size_t)(m0 + ar) * SS + ac;

    for (int k0 = 0; k0 < Kend; k0 += 8) {
        float4 av  = *(const float4*)(Ap + k0);
        float4 bvv = *(const float4*)(Bv + (size_t)(k0 + br) * HD + bc);
        __syncthreads();
        As[ac + 0][ar] = av.x; As[ac + 1][ar] = av.y;
        As[ac + 2][ar] = av.z; As[ac + 3][ar] = av.w;
        *(float4*)&Bs[br][bc] = bvv;
        __syncthreads();
#pragma unroll
        for (int k = 0; k < 8; k++) {
            float a[8], b[8];
            *(float4*)(a)     = *(const float4*)&As[k][ty * 4];
            *(float4*)(a + 4) = *(const float4*)&As[k][64 + ty * 4];
            *(float4*)(b)     = *(const float4*)&Bs[k][tx * 4];
            *(float4*)(b + 4) = *(const float4*)&Bs[k][64 + tx * 4];
#pragma unroll
            for (int i = 0; i < 8; i++)
#pragma unroll
                for (int j = 0; j < 8; j++) acc[i][j] += a[i] * b[j];
        }
    }
#pragma unroll
    for (int i = 0; i < 8; i++) {
        int m = m0 + ((i < 4) ? (ty * 4 + i) : (64 + ty * 4 + (i - 4)));
        float4 o0 = make_float4(acc[i][0], acc[i][1], acc[i][2], acc[i][3]);
        float4 o1 = make_float4(acc[i][4], acc[i][5], acc[i][6], acc[i][7]);
        *(float4*)&C[(size_t)m * (HQ * HD) + tx * 4]      = o0;
        *(float4*)&C[(size_t)m * (HQ * HD) + 64 + tx * 4] = o1;
    }
}

// ============================== launch ======================================
extern "C" void kernel_launch(void* const* d_in, const int* in_sizes, int n_in,
                              void* d_out, int out_size)
{
    const float* hs   = (const float*)d_in[0];
    const float* cosb = (const float*)d_in[1];
    const float* sinb = (const float*)d_in[2];
    // d_in[3] = attention_mask (causal; recomputed analytically, unused)
    const float* Wq   = (const float*)d_in[4];
    const float* Wk   = (const float*)d_in[5];
    const float* Wv   = (const float*)d_in[6];
    const float* Wo   = (const float*)d_in[7];
    const float* qw   = (const float*)d_in[8];
    const float* kw   = (const float*)d_in[9];
    float* out = (float*)d_out;

    float *qlin, *klin, *vlin, *qr, *kr, *vr, *osc, *wfall;
    cudaGetSymbolAddress((void**)&qlin, g_qlin);
    cudaGetSymbolAddress((void**)&klin, g_klin);
    cudaGetSymbolAddress((void**)&vlin, g_vlin);
    cudaGetSymbolAddress((void**)&qr,   g_q);
    cudaGetSymbolAddress((void**)&kr,   g_k);
    cudaGetSymbolAddress((void**)&vr,   g_v);
    cudaGetSymbolAddress((void**)&osc,  g_o);
    cudaGetSymbolAddress((void**)&wfall, g_wfall);

    const size_t OUT_ELEMS = (size_t)NTOK * DD;              // 4,194,304
    const size_t W_ELEMS   = (size_t)BB * HQ * SS * SS;      // 134,217,728
    float* wptr = ((size_t)out_size >= OUT_ELEMS + W_ELEMS) ? (out + OUT_ELEMS)
                                                            : wfall;

    dim3 blk(256);
    // QKV projections
    gemm_nt_kernel<<<dim3(HQ * HD / 128, NTOK / 128), blk>>>(hs, Wq, qlin, DD, DD, DD, HQ * HD);
    gemm_nt_kernel<<<dim3(HKV * HD / 128, NTOK / 128), blk>>>(hs, Wk, klin, DD, DD, DD, HKV * HD);
    gemm_nt_kernel<<<dim3(HKV * HD / 128, NTOK / 128), blk>>>(hs, Wv, vlin, DD, DD, DD, HKV * HD);
    // RMSNorm + RoPE + V relayout
    rmsrope_kernel<<<dim3(NTOK, HQ + HKV), 128>>>(qlin, klin, vlin, cosb, sinb,
                                                  qw, kw, qr, kr, vr);
    // scores -> weights region (causal block skip)
    scores_kernel<<<dim3(SS / 128, SS / 128, NBH), blk>>>(qr, kr, wptr);
    // in-place causal softmax
    softmax_kernel<<<(unsigned)(NBH * SS), blk>>>(wptr);
    // AV
    av_kernel<<<dim3(1, SS / 128, NBH), blk>>>(wptr, vr, osc);
    // output projection
    gemm_nt_kernel<<<dim3(DD / 128, NTOK / 128), blk>>>(osc, Wo, out, HQ * HD, HQ * HD, HQ * HD, DD);
}

// round 3
// speedup vs baseline: 1.8659x; 1.8659x over previous
#include <cuda_runtime.h>
#include <cstdint>

#define BB   2
#define SS   2048
#define DD   1024
#define HQ   16
#define HKV  8
#define HD   128
#define NTOK (BB*SS)     /* 4096 */
#define NBH  (BB*HQ)     /* 32   */

// ---------------- device scratch (static globals; no runtime allocation) ----
__device__ float g_qlin[(size_t)NTOK * HQ  * HD];
__device__ float g_klin[(size_t)NTOK * HKV * HD];
__device__ float g_vlin[(size_t)NTOK * HKV * HD];
__device__ float g_q  [(size_t)BB * HQ  * SS * HD];
__device__ float g_k  [(size_t)BB * HKV * SS * HD];
__device__ float g_v  [(size_t)BB * HKV * SS * HD];
__device__ float g_o  [(size_t)NTOK * HQ * HD];
__device__ float g_wfall[(size_t)BB * HQ * SS * SS];

// ---------------------------------------------------------------------------
__device__ __forceinline__ uint32_t f2tf32(float x) {
    uint32_t r; asm("cvt.rna.tf32.f32 %0, %1;" : "=r"(r) : "f"(x)); return r;
}
__device__ __forceinline__ void mma8(float* d, const uint32_t* a, const uint32_t* b) {
    asm volatile("mma.sync.aligned.m16n8k8.row.col.f32.tf32.tf32.f32 "
        "{%0,%1,%2,%3}, {%4,%5,%6,%7}, {%8,%9}, {%0,%1,%2,%3};"
        : "+f"(d[0]), "+f"(d[1]), "+f"(d[2]), "+f"(d[3])
        : "r"(a[0]), "r"(a[1]), "r"(a[2]), "r"(a[3]), "r"(b[0]), "r"(b[1]));
}

// 128x128 block tile, 256 threads (8 warps, 2x4), warp tile 64x32.
// A: row-major MxK (tile base pre-offset). B: NN==0 -> [n][k] (NT);
// NN==1 -> [k][n]. 3xTF32 split for fp32-grade accuracy on tensor cores.
template<int NN>
__device__ __forceinline__ void gemm_core(
    const float* __restrict__ A, const float* __restrict__ B,
    float* __restrict__ C, int lda, int ldb, int ldc,
    int kIters, float alpha)
{
    __shared__ uint32_t AsH[2][8][32][4];
    __shared__ uint32_t AsL[2][8][32][4];
    __shared__ uint32_t BsH[2][16][32][2];
    __shared__ uint32_t BsL[2][16][32][2];

    const int t = threadIdx.x;
    const int lane = t & 31;
    const int warp = t >> 5;
    const int wm = warp >> 2;   // 0..1
    const int wn = warp & 3;    // 0..3

    float acc[4][4][4];
#pragma unroll
    for (int i = 0; i < 4; i++)
#pragma unroll
        for (int j = 0; j < 4; j++)
#pragma unroll
            for (int r = 0; r < 4; r++) acc[i][j][r] = 0.f;

    // A loader: thread -> row mA, k-group kg (covers k +0..3 of each k8)
    const int mA = t >> 1, kg = t & 1;
    const float* Ap = A + (size_t)mA * lda + kg * 4;
    const int a_mfrag = mA >> 4;
    const int a_lane  = (mA & 7) * 4;
    const int a_reg   = kg * 2 + ((mA >> 3) & 1);

    // B loader
    const float* Bp0; const float* Bp1;
    int b_kt = 0, b_q = 0, b_ch = 0, b_n0 = 0, b_nfrag = 0, b_lb = 0;
    if (NN) {
        const int kB = t & 15;
        b_n0 = (t >> 4) * 4;
        Bp0  = B + (size_t)kB * ldb + b_n0;
        Bp1  = Bp0 + 64;
        b_kt = kB >> 3; b_q = kB & 3; b_ch = (kB >> 2) & 1;
    } else {
        const int nB = t >> 1;
        Bp0 = B + (size_t)nB * ldb + kg * 4;
        Bp1 = Bp0 + 8;
        b_nfrag = nB >> 3; b_lb = (nB & 7) * 4;
    }

    float ax[8], bx2[8];
    // preload iter 0
    {
        float4 r0 = *(const float4*)(Ap);
        float4 r1 = *(const float4*)(Ap + 8);
        ax[0]=r0.x; ax[1]=r0.y; ax[2]=r0.z; ax[3]=r0.w;
        ax[4]=r1.x; ax[5]=r1.y; ax[6]=r1.z; ax[7]=r1.w;
        float4 s0 = *(const float4*)(Bp0);
        float4 s1 = *(const float4*)(Bp1);
        bx2[0]=s0.x; bx2[1]=s0.y; bx2[2]=s0.z; bx2[3]=s0.w;
        bx2[4]=s1.x; bx2[5]=s1.y; bx2[6]=s1.z; bx2[7]=s1.w;
    }

    for (int it = 0; it < kIters; ++it) {
        __syncthreads();
        // scatter A (both k8 sub-tiles)
#pragma unroll
        for (int kt = 0; kt < 2; kt++) {
#pragma unroll
            for (int j = 0; j < 4; j++) {
                float x = ax[kt * 4 + j];
                uint32_t hi = f2tf32(x);
                uint32_t lo = f2tf32(x - __uint_as_float(hi));
                AsH[kt][a_mfrag][a_lane + j][a_reg] = hi;
                AsL[kt][a_mfrag][a_lane + j][a_reg] = lo;
            }
        }
        // scatter B
        if (NN) {
#pragma unroll
            for (int h = 0; h < 2; h++) {
#pragma unroll
                for (int j = 0; j < 4; j++) {
                    int nj = b_n0 + h * 64 + j;
                    float x = bx2[h * 4 + j];
                    uint32_t hi = f2tf32(x);
                    uint32_t lo = f2tf32(x - __uint_as_float(hi));
                    BsH[b_kt][nj >> 3][(nj & 7) * 4 + b_q][b_ch] = hi;
                    BsL[b_kt][nj >> 3][(nj & 7) * 4 + b_q][b_ch] = lo;
                }
            }
        } else {
#pragma unroll
            for (int kt = 0; kt < 2; kt++) {
#pragma unroll
                for (int j = 0; j < 4; j++) {
                    float x = bx2[kt * 4 + j];
                    uint32_t hi = f2tf32(x);
                    uint32_t lo = f2tf32(x - __uint_as_float(hi));
                    BsH[kt][b_nfrag][b_lb + j][kg] = hi;
                    BsL[kt][b_nfrag][b_lb + j][kg] = lo;
                }
            }
        }
        __syncthreads();
        // preload next iter (overlaps with compute below)
        if (it + 1 < kIters) {
            int k0 = (it + 1) * 16;
            float4 r0 = *(const float4*)(Ap + k0);
            float4 r1 = *(const float4*)(Ap + k0 + 8);
            ax[0]=r0.x; ax[1]=r0.y; ax[2]=r0.z; ax[3]=r0.w;
            ax[4]=r1.x; ax[5]=r1.y; ax[6]=r1.z; ax[7]=r1.w;
            float4 s0, s1;
            if (NN) {
                s0 = *(const float4*)(Bp0 + (size_t)k0 * ldb);
                s1 = *(const float4*)(Bp1 + (size_t)k0 * ldb);
            } else {
                s0 = *(const float4*)(Bp0 + k0);
                s1 = *(const float4*)(Bp1 + k0);
            }
            bx2[0]=s0.x; bx2[1]=s0.y; bx2[2]=s0.z; bx2[3]=s0.w;
            bx2[4]=s1.x; bx2[5]=s1.y; bx2[6]=s1.z; bx2[7]=s1.w;
        }
        // compute both k8 sub-tiles
#pragma unroll
        for (int kt = 0; kt < 2; kt++) {
            uint32_t ah[4][4], al[4][4];
#pragma unroll
            for (int i = 0; i < 4; i++) {
                uint4 h = *(const uint4*)&AsH[kt][wm * 4 + i][lane][0];
                ah[i][0] = h.x; ah[i][1] = h.y; ah[i][2] = h.z; ah[i][3] = h.w;
                uint4 l = *(const uint4*)&AsL[kt][wm * 4 + i][lane][0];
                al[i][0] = l.x; al[i][1] = l.y; al[i][2] = l.z; al[i][3] = l.w;
            }
            uint32_t bh[4][2], bl[4][2];
#pragma unroll
            for (int j = 0; j < 4; j++) {
                uint2 h = *(const uint2*)&BsH[kt][wn * 4 + j][lane][0];
                bh[j][0] = h.x; bh[j][1] = h.y;
                uint2 l = *(const uint2*)&BsL[kt][wn * 4 + j][lane][0];
                bl[j][0] = l.x; bl[j][1] = l.y;
            }
#pragma unroll
            for (int i = 0; i < 4; i++)
#pragma unroll
                for (int j = 0; j < 4; j++) {
                    mma8(acc[i][j], al[i], bh[j]);
                    mma8(acc[i][j], ah[i], bl[j]);
                    mma8(acc[i][j], ah[i], bh[j]);
                }
        }
    }
    // epilogue
    const int g = lane >> 2, q = lane & 3;
#pragma unroll
    for (int i = 0; i < 4; i++) {
        int r0 = wm * 64 + i * 16 + g;
#pragma unroll
        for (int j = 0; j < 4; j++) {
            int col = wn * 32 + j * 8 + q * 2;
            float2 v0 = make_float2(acc[i][j][0] * alpha, acc[i][j][1] * alpha);
            float2 v1 = make_float2(acc[i][j][2] * alpha, acc[i][j][3] * alpha);
            *(float2*)&C[(size_t)r0 * ldc + col]       = v0;
            *(float2*)&C[(size_t)(r0 + 8) * ldc + col] = v1;
        }
    }
}

// ---------------- kernel wrappers ------------------------------------------
__global__ void __launch_bounds__(256) gemm_nt_mma(
    const float* __restrict__ A, const float* __restrict__ B,
    float* __restrict__ C, int K, int lda, int ldb, int ldc)
{
    gemm_core<0>(A + (size_t)blockIdx.y * 128 * lda,
                 B + (size_t)blockIdx.x * 128 * ldb,
                 C + (size_t)blockIdx.y * 128 * ldc + blockIdx.x * 128,
                 lda, ldb, ldc, K / 16, 1.f);
}

__global__ void __launch_bounds__(256) scores_mma(
    const float* __restrict__ Q, const float* __restrict__ Kk,
    float* __restrict__ W)
{
    const int bx = blockIdx.x, by = blockIdx.y, z = blockIdx.z;
    if (bx > by) return;
    const int kvz = (z >> 4) * HKV + ((z & 15) >> 1);
    gemm_core<0>(Q  + ((size_t)z   * SS + by * 128) * HD,
                 Kk + ((size_t)kvz * SS + bx * 128) * HD,
                 W + (size_t)z * SS * SS + (size_t)by * 128 * SS + bx * 128,
                 HD, HD, SS, HD / 16, 0.08838834764831845f);
}

__global__ void __launch_bounds__(256) av_mma(
    const float* __restrict__ W, const float* __restrict__ V,
    float* __restrict__ O)
{
    const int my = blockIdx.y, z = blockIdx.z;
    const int kvz = (z >> 4) * HKV + ((z & 15) >> 1);
    const int kIters = (my + 1) * 8;     // causal K bound: (my+1)*128 / 16
    gemm_core<1>(W + (size_t)z * SS * SS + (size_t)my * 128 * SS,
                 V + (size_t)kvz * SS * HD,
                 O + (size_t)(z >> 4) * SS * (HQ * HD)
                   + (size_t)my * 128 * (HQ * HD) + (z & 15) * HD,
                 SS, HD, HQ * HD, kIters, 1.f);
}

// ======== RMSNorm + RoPE (+ V relayout). Grid (NTOK, 24), 128 threads ======
__global__ void rmsrope_kernel(const float* __restrict__ qlin,
                               const float* __restrict__ klin,
                               const float* __restrict__ vlin,
                               const float* __restrict__ cosb,
                               const float* __restrict__ sinb,
                               const float* __restrict__ qw,
                               const float* __restrict__ kw,
                               float* __restrict__ qout,
                               float* __restrict__ kout,
                               float* __restrict__ vout)
{
    const int token = blockIdx.x;
    const int y     = blockIdx.y;
    const int i     = threadIdx.x;
    const int b = token >> 11, s = token & (SS - 1);
    __shared__ float sh[128];
    __shared__ float red[4];

    float c  = cosb[(size_t)token * HD + i];
    float sn = sinb[(size_t)token * HD + i];
    float x, w;
    float* outp;
    if (y < HQ) {
        x = qlin[(size_t)token * (HQ * HD) + y * HD + i];
        w = qw[i];
        outp = qout + (((size_t)(b * HQ + y)) * SS + s) * HD;
    } else {
        int h = y - HQ;
        x = klin[(size_t)token * (HKV * HD) + h * HD + i];
        w = kw[i];
        outp = kout + (((size_t)(b * HKV + h)) * SS + s) * HD;
        vout[(((size_t)(b * HKV + h)) * SS + s) * HD + i] =
            vlin[(size_t)token * (HKV * HD) + h * HD + i];
    }
    float ss = x * x;
#pragma unroll
    for (int off = 16; off; off >>= 1) ss += __shfl_xor_sync(0xffffffffu, ss, off);
    const int lane = i & 31, wid = i >> 5;
    if (lane == 0) red[wid] = ss;
    __syncthreads();
    ss = red[0] + red[1] + red[2] + red[3];
    float inv = rsqrtf(ss * (1.f / HD) + 1e-6f);
    float xn  = x * inv * w;
    sh[i] = xn;
    __syncthreads();
    float rot = (i < 64) ? -sh[i + 64] : sh[i - 64];
    outp[i] = xn * c + rot * sn;
}

// ======= in-place causal softmax. Grid B*HQ*SS, 256 threads ================
__global__ void softmax_kernel(float* __restrict__ W)
{
    const size_t row = blockIdx.x;
    const int iq = (int)(row & (SS - 1));
    float* p = W + row * SS;
    const int L = iq + 1;
    const int t = threadIdx.x;
    __shared__ float red[8];

    float v[8];
#pragma unroll
    for (int r = 0; r < 8; r++) v[r] = p[t + r * 256];

    float m = -3.4e38f;
#pragma unroll
    for (int r = 0; r < 8; r++)
        if (t + r * 256 < L) m = fmaxf(m, v[r]);
#pragma unroll
    for (int off = 16; off; off >>= 1) m = fmaxf(m, __shfl_xor_sync(0xffffffffu, m, off));
    if ((t & 31) == 0) red[t >> 5] = m;
    __syncthreads();
    m = red[0];
#pragma unroll
    for (int wq = 1; wq < 8; wq++) m = fmaxf(m, red[wq]);
    __syncthreads();

    float ssum = 0.f;
#pragma unroll
    for (int r = 0; r < 8; r++) {
        int j = t + r * 256;
        float e = (j < L) ? __expf(v[r] - m) : 0.f;
        v[r] = e;
        ssum += e;
    }
#pragma unroll
    for (int off = 16; off; off >>= 1) ssum += __shfl_xor_sync(0xffffffffu, ssum, off);
    if ((t & 31) == 0) red[t >> 5] = ssum;
    __syncthreads();
    ssum = red[0] + red[1] + red[2] + red[3] + red[4] + red[5] + red[6] + red[7];
    const float inv = 1.f / ssum;

#pragma unroll
    for (int r = 0; r < 8; r++) p[t + r * 256] = v[r] * inv;
}

// ============================== launch ======================================
extern "C" void kernel_launch(void* const* d_in, const int* in_sizes, int n_in,
                              void* d_out, int out_size)
{
    const float* hs   = (const float*)d_in[0];
    const float* cosb = (const float*)d_in[1];
    const float* sinb = (const float*)d_in[2];
    const float* Wq   = (const float*)d_in[4];
    const float* Wk   = (const float*)d_in[5];
    const float* Wv   = (const float*)d_in[6];
    const float* Wo   = (const float*)d_in[7];
    const float* qw   = (const float*)d_in[8];
    const float* kw   = (const float*)d_in[9];
    float* out = (float*)d_out;

    float *qlin, *klin, *vlin, *qr, *kr, *vr, *osc, *wfall;
    cudaGetSymbolAddress((void**)&qlin, g_qlin);
    cudaGetSymbolAddress((void**)&klin, g_klin);
    cudaGetSymbolAddress((void**)&vlin, g_vlin);
    cudaGetSymbolAddress((void**)&qr,   g_q);
    cudaGetSymbolAddress((void**)&kr,   g_k);
    cudaGetSymbolAddress((void**)&vr,   g_v);
    cudaGetSymbolAddress((void**)&osc,  g_o);
    cudaGetSymbolAddress((void**)&wfall, g_wfall);

    const size_t OUT_ELEMS = (size_t)NTOK * DD;
    const size_t W_ELEMS   = (size_t)BB * HQ * SS * SS;
    float* wptr = ((size_t)out_size >= OUT_ELEMS + W_ELEMS) ? (out + OUT_ELEMS)
                                                            : wfall;

    dim3 blk(256);
    // QKV projections (tf32 3x tensor-core GEMM)
    gemm_nt_mma<<<dim3(HQ * HD / 128, NTOK / 128), blk>>>(hs, Wq, qlin, DD, DD, DD, HQ * HD);
    gemm_nt_mma<<<dim3(HKV * HD / 128, NTOK / 128), blk>>>(hs, Wk, klin, DD, DD, DD, HKV * HD);
    gemm_nt_mma<<<dim3(HKV * HD / 128, NTOK / 128), blk>>>(hs, Wv, vlin, DD, DD, DD, HKV * HD);
    // RMSNorm + RoPE + V relayout
    rmsrope_kernel<<<dim3(NTOK, HQ + HKV), 128>>>(qlin, klin, vlin, cosb, sinb,
                                                  qw, kw, qr, kr, vr);
    // scores -> weights region (causal block skip)
    scores_mma<<<dim3(SS / 128, SS / 128, NBH), blk>>>(qr, kr, wptr);
    // in-place causal softmax
    softmax_kernel<<<(unsigned)(NBH * SS), blk>>>(wptr);
    // AV (causal K bound)
    av_mma<<<dim3(1, SS / 128, NBH), blk>>>(wptr, vr, osc);
    // output projection
    gemm_nt_mma<<<dim3(DD / 128, NTOK / 128), blk>>>(osc, Wo, out, HQ * HD, HQ * HD, HQ * HD, DD);
}

// round 4
// speedup vs baseline: 3.0662x; 1.6433x over previous
#include <cuda_runtime.h>
#include <cstdint>

#define BB   2
#define SS   2048
#define DD   1024
#define HQ   16
#define HKV  8
#define HD   128
#define NTOK (BB*SS)     /* 4096 */
#define NBH  (BB*HQ)     /* 32   */

// ---------------- device scratch (static globals; no runtime allocation) ----
__device__ float g_qlin[(size_t)NTOK * HQ  * HD];
__device__ float g_klin[(size_t)NTOK * HKV * HD];
__device__ float g_vlin[(size_t)NTOK * HKV * HD];
__device__ float g_q  [(size_t)BB * HQ  * SS * HD];
__device__ float g_k  [(size_t)BB * HKV * SS * HD];
__device__ float g_v  [(size_t)BB * HKV * SS * HD];
__device__ float g_o  [(size_t)NTOK * HQ * HD];
__device__ float g_wfall[(size_t)BB * HQ * SS * SS];

// ---------------------------------------------------------------------------
__device__ __forceinline__ uint32_t f2tf32(float x) {
    uint32_t r; asm("cvt.rna.tf32.f32 %0, %1;" : "=r"(r) : "f"(x)); return r;
}
__device__ __forceinline__ void mma8(float* d, const uint32_t* a, const uint32_t* b) {
    asm volatile("mma.sync.aligned.m16n8k8.row.col.f32.tf32.tf32.f32 "
        "{%0,%1,%2,%3}, {%4,%5,%6,%7}, {%8,%9}, {%0,%1,%2,%3};"
        : "+f"(d[0]), "+f"(d[1]), "+f"(d[2]), "+f"(d[3])
        : "r"(a[0]), "r"(a[1]), "r"(a[2]), "r"(a[3]), "r"(b[0]), "r"(b[1]));
}

// 128x128 block tile, 256 threads (8 warps, 2x4), warp tile 64x32.
// Single-pass TF32, double-buffered smem (one barrier per k16 iter).
// A: row-major MxK (tile base pre-offset). B: NN==0 -> [n][k] (NT);
// NN==1 -> [k][n].
template<int NN>
__device__ __forceinline__ void gemm_core(
    const float* __restrict__ A, const float* __restrict__ B,
    float* __restrict__ C, int lda, int ldb, int ldc,
    int kIters, float alpha)
{
    __shared__ uint32_t AsH[2][2][8][32][4];   // [stage][kt][mfrag][lane][reg]
    __shared__ uint32_t BsH[2][2][16][32][2];  // [stage][kt][nfrag][lane][reg]

    const int t = threadIdx.x;
    const int lane = t & 31;
    const int warp = t >> 5;
    const int wm = warp >> 2;   // 0..1
    const int wn = warp & 3;    // 0..3

    float acc[4][4][4];
#pragma unroll
    for (int i = 0; i < 4; i++)
#pragma unroll
        for (int j = 0; j < 4; j++)
#pragma unroll
            for (int r = 0; r < 4; r++) acc[i][j][r] = 0.f;

    // A loader: thread -> row mA, k-group kg (covers k +0..3 of each k8)
    const int mA = t >> 1, kg = t & 1;
    const float* Ap = A + (size_t)mA * lda + kg * 4;
    const int a_mfrag = mA >> 4;
    const int a_lane  = (mA & 7) * 4;
    const int a_reg   = kg * 2 + ((mA >> 3) & 1);

    // B loader
    const float* Bp0; const float* Bp1;
    int b_kt = 0, b_q = 0, b_ch = 0, b_n0 = 0, b_nfrag = 0, b_lb = 0;
    if (NN) {
        const int kB = t & 15;
        b_n0 = (t >> 4) * 4;
        Bp0  = B + (size_t)kB * ldb + b_n0;
        Bp1  = Bp0 + 64;
        b_kt = kB >> 3; b_q = kB & 3; b_ch = (kB >> 2) & 1;
    } else {
        const int nB = t >> 1;
        Bp0 = B + (size_t)nB * ldb + kg * 4;
        Bp1 = Bp0 + 8;
        b_nfrag = nB >> 3; b_lb = (nB & 7) * 4;
    }

    float ax[8], bx2[8];
    // preload iter 0
    {
        float4 r0 = *(const float4*)(Ap);
        float4 r1 = *(const float4*)(Ap + 8);
        ax[0]=r0.x; ax[1]=r0.y; ax[2]=r0.z; ax[3]=r0.w;
        ax[4]=r1.x; ax[5]=r1.y; ax[6]=r1.z; ax[7]=r1.w;
        float4 s0 = *(const float4*)(Bp0);
        float4 s1 = *(const float4*)(Bp1);
        bx2[0]=s0.x; bx2[1]=s0.y; bx2[2]=s0.z; bx2[3]=s0.w;
        bx2[4]=s1.x; bx2[5]=s1.y; bx2[6]=s1.z; bx2[7]=s1.w;
    }

    for (int it = 0; it < kIters; ++it) {
        const int st = it & 1;
        // scatter A (both k8 sub-tiles)
#pragma unroll
        for (int kt = 0; kt < 2; kt++) {
#pragma unroll
            for (int j = 0; j < 4; j++)
                AsH[st][kt][a_mfrag][a_lane + j][a_reg] = f2tf32(ax[kt * 4 + j]);
        }
        // scatter B
        if (NN) {
#pragma unroll
            for (int h = 0; h < 2; h++) {
#pragma unroll
                for (int j = 0; j < 4; j++) {
                    int nj = b_n0 + h * 64 + j;
                    BsH[st][b_kt][nj >> 3][(nj & 7) * 4 + b_q][b_ch] = f2tf32(bx2[h * 4 + j]);
                }
            }
        } else {
#pragma unroll
            for (int kt = 0; kt < 2; kt++) {
#pragma unroll
                for (int j = 0; j < 4; j++)
                    BsH[st][kt][b_nfrag][b_lb + j][kg] = f2tf32(bx2[kt * 4 + j]);
            }
        }
        __syncthreads();
        // preload next iter (overlaps with compute below)
        if (it + 1 < kIters) {
            int k0 = (it + 1) * 16;
            float4 r0 = *(const float4*)(Ap + k0);
            float4 r1 = *(const float4*)(Ap + k0 + 8);
            ax[0]=r0.x; ax[1]=r0.y; ax[2]=r0.z; ax[3]=r0.w;
            ax[4]=r1.x; ax[5]=r1.y; ax[6]=r1.z; ax[7]=r1.w;
            float4 s0, s1;
            if (NN) {
                s0 = *(const float4*)(Bp0 + (size_t)k0 * ldb);
                s1 = *(const float4*)(Bp1 + (size_t)k0 * ldb);
            } else {
                s0 = *(const float4*)(Bp0 + k0);
                s1 = *(const float4*)(Bp1 + k0);
            }
            bx2[0]=s0.x; bx2[1]=s0.y; bx2[2]=s0.z; bx2[3]=s0.w;
            bx2[4]=s1.x; bx2[5]=s1.y; bx2[6]=s1.z; bx2[7]=s1.w;
        }
        // compute both k8 sub-tiles (single-pass tf32)
#pragma unroll
        for (int kt = 0; kt < 2; kt++) {
            uint32_t ah[4][4];
#pragma unroll
            for (int i = 0; i < 4; i++) {
                uint4 h = *(const uint4*)&AsH[st][kt][wm * 4 + i][lane][0];
                ah[i][0] = h.x; ah[i][1] = h.y; ah[i][2] = h.z; ah[i][3] = h.w;
            }
            uint32_t bh[4][2];
#pragma unroll
            for (int j = 0; j < 4; j++) {
                uint2 h = *(const uint2*)&BsH[st][kt][wn * 4 + j][lane][0];
                bh[j][0] = h.x; bh[j][1] = h.y;
            }
#pragma unroll
            for (int i = 0; i < 4; i++)
#pragma unroll
                for (int j = 0; j < 4; j++)
                    mma8(acc[i][j], ah[i], bh[j]);
        }
    }
    // epilogue
    const int g = lane >> 2, q = lane & 3;
#pragma unroll
    for (int i = 0; i < 4; i++) {
        int r0 = wm * 64 + i * 16 + g;
#pragma unroll
        for (int j = 0; j < 4; j++) {
            int col = wn * 32 + j * 8 + q * 2;
            float2 v0 = make_float2(acc[i][j][0] * alpha, acc[i][j][1] * alpha);
            float2 v1 = make_float2(acc[i][j][2] * alpha, acc[i][j][3] * alpha);
            *(float2*)&C[(size_t)r0 * ldc + col]       = v0;
            *(float2*)&C[(size_t)(r0 + 8) * ldc + col] = v1;
        }
    }
}

// ---------------- kernel wrappers ------------------------------------------
__global__ void __launch_bounds__(256) gemm_nt_mma(
    const float* __restrict__ A, const float* __restrict__ B,
    float* __restrict__ C, int K, int lda, int ldb, int ldc)
{
    gemm_core<0>(A + (size_t)blockIdx.y * 128 * lda,
                 B + (size_t)blockIdx.x * 128 * ldb,
                 C + (size_t)blockIdx.y * 128 * ldc + blockIdx.x * 128,
                 lda, ldb, ldc, K / 16, 1.f);
}

__global__ void __launch_bounds__(256) scores_mma(
    const float* __restrict__ Q, const float* __restrict__ Kk,
    float* __restrict__ W)
{
    const int bx = blockIdx.x, by = blockIdx.y, z = blockIdx.z;
    if (bx > by) return;
    const int kvz = (z >> 4) * HKV + ((z & 15) >> 1);
    gemm_core<0>(Q  + ((size_t)z   * SS + by * 128) * HD,
                 Kk + ((size_t)kvz * SS + bx * 128) * HD,
                 W + (size_t)z * SS * SS + (size_t)by * 128 * SS + bx * 128,
                 HD, HD, SS, HD / 16, 0.08838834764831845f);
}

__global__ void __launch_bounds__(256) av_mma(
    const float* __restrict__ W, const float* __restrict__ V,
    float* __restrict__ O)
{
    const int my = blockIdx.y, z = blockIdx.z;
    const int kvz = (z >> 4) * HKV + ((z & 15) >> 1);
    const int kIters = (my + 1) * 8;     // causal K bound: (my+1)*128 / 16
    gemm_core<1>(W + (size_t)z * SS * SS + (size_t)my * 128 * SS,
                 V + (size_t)kvz * SS * HD,
                 O + (size_t)(z >> 4) * SS * (HQ * HD)
                   + (size_t)my * 128 * (HQ * HD) + (z & 15) * HD,
                 SS, HD, HQ * HD, kIters, 1.f);
}

// ======== RMSNorm + RoPE (+ V relayout). Grid (NTOK, 24), 128 threads ======
__global__ void rmsrope_kernel(const float* __restrict__ qlin,
                               const float* __restrict__ klin,
                               const float* __restrict__ vlin,
                               const float* __restrict__ cosb,
                               const float* __restrict__ sinb,
                               const float* __restrict__ qw,
                               const float* __restrict__ kw,
                               float* __restrict__ qout,
                               float* __restrict__ kout,
                               float* __restrict__ vout)
{
    const int token = blockIdx.x;
    const int y     = blockIdx.y;
    const int i     = threadIdx.x;
    const int b = token >> 11, s = token & (SS - 1);
    __shared__ float sh[128];
    __shared__ float red[4];

    float c  = cosb[(size_t)token * HD + i];
    float sn = sinb[(size_t)token * HD + i];
    float x, w;
    float* outp;
    if (y < HQ) {
        x = qlin[(size_t)token * (HQ * HD) + y * HD + i];
        w = qw[i];
        outp = qout + (((size_t)(b * HQ + y)) * SS + s) * HD;
    } else {
        int h = y - HQ;
        x = klin[(size_t)token * (HKV * HD) + h * HD + i];
        w = kw[i];
        outp = kout + (((size_t)(b * HKV + h)) * SS + s) * HD;
        vout[(((size_t)(b * HKV + h)) * SS + s) * HD + i] =
            vlin[(size_t)token * (HKV * HD) + h * HD + i];
    }
    float ss = x * x;
#pragma unroll
    for (int off = 16; off; off >>= 1) ss += __shfl_xor_sync(0xffffffffu, ss, off);
    const int lane = i & 31, wid = i >> 5;
    if (lane == 0) red[wid] = ss;
    __syncthreads();
    ss = red[0] + red[1] + red[2] + red[3];
    float inv = rsqrtf(ss * (1.f / HD) + 1e-6f);
    float xn  = x * inv * w;
    sh[i] = xn;
    __syncthreads();
    float rot = (i < 64) ? -sh[i + 64] : sh[i - 64];
    outp[i] = xn * c + rot * sn;
}

// ======= in-place causal softmax. Grid B*HQ*SS, 256 threads ================
__global__ void softmax_kernel(float* __restrict__ W)
{
    const size_t row = blockIdx.x;
    const int iq = (int)(row & (SS - 1));
    float* p = W + row * SS;
    const int L = iq + 1;
    const int t = threadIdx.x;
    __shared__ float red[8];

    float v[8];
#pragma unroll
    for (int r = 0; r < 8; r++) v[r] = p[t + r * 256];

    float m = -3.4e38f;
#pragma unroll
    for (int r = 0; r < 8; r++)
        if (t + r * 256 < L) m = fmaxf(m, v[r]);
#pragma unroll
    for (int off = 16; off; off >>= 1) m = fmaxf(m, __shfl_xor_sync(0xffffffffu, m, off));
    if ((t & 31) == 0) red[t >> 5] = m;
    __syncthreads();
    m = red[0];
#pragma unroll
    for (int wq = 1; wq < 8; wq++) m = fmaxf(m, red[wq]);
    __syncthreads();

    float ssum = 0.f;
#pragma unroll
    for (int r = 0; r < 8; r++) {
        int j = t + r * 256;
        float e = (j < L) ? __expf(v[r] - m) : 0.f;
        v[r] = e;
        ssum += e;
    }
#pragma unroll
    for (int off = 16; off; off >>= 1) ssum += __shfl_xor_sync(0xffffffffu, ssum, off);
    if ((t & 31) == 0) red[t >> 5] = ssum;
    __syncthreads();
    ssum = red[0] + red[1] + red[2] + red[3] + red[4] + red[5] + red[6] + red[7];
    const float inv = 1.f / ssum;

#pragma unroll
    for (int r = 0; r < 8; r++) p[t + r * 256] = v[r] * inv;
}

// ============================== launch ======================================
extern "C" void kernel_launch(void* const* d_in, const int* in_sizes, int n_in,
                              void* d_out, int out_size)
{
    const float* hs   = (const float*)d_in[0];
    const float* cosb = (const float*)d_in[1];
    const float* sinb = (const float*)d_in[2];
    const float* Wq   = (const float*)d_in[4];
    const float* Wk   = (const float*)d_in[5];
    const float* Wv   = (const float*)d_in[6];
    const float* Wo   = (const float*)d_in[7];
    const float* qw   = (const float*)d_in[8];
    const float* kw   = (const float*)d_in[9];
    float* out = (float*)d_out;

    float *qlin, *klin, *vlin, *qr, *kr, *vr, *osc, *wfall;
    cudaGetSymbolAddress((void**)&qlin, g_qlin);
    cudaGetSymbolAddress((void**)&klin, g_klin);
    cudaGetSymbolAddress((void**)&vlin, g_vlin);
    cudaGetSymbolAddress((void**)&qr,   g_q);
    cudaGetSymbolAddress((void**)&kr,   g_k);
    cudaGetSymbolAddress((void**)&vr,   g_v);
    cudaGetSymbolAddress((void**)&osc,  g_o);
    cudaGetSymbolAddress((void**)&wfall, g_wfall);

    const size_t OUT_ELEMS = (size_t)NTOK * DD;
    const size_t W_ELEMS   = (size_t)BB * HQ * SS * SS;
    float* wptr = ((size_t)out_size >= OUT_ELEMS + W_ELEMS) ? (out + OUT_ELEMS)
                                                            : wfall;

    dim3 blk(256);
    // QKV projections (tf32 tensor-core GEMM)
    gemm_nt_mma<<<dim3(HQ * HD / 128, NTOK / 128), blk>>>(hs, Wq, qlin, DD, DD, DD, HQ * HD);
    gemm_nt_mma<<<dim3(HKV * HD / 128, NTOK / 128), blk>>>(hs, Wk, klin, DD, DD, DD, HKV * HD);
    gemm_nt_mma<<<dim3(HKV * HD / 128, NTOK / 128), blk>>>(hs, Wv, vlin, DD, DD, DD, HKV * HD);
    // RMSNorm + RoPE + V relayout
    rmsrope_kernel<<<dim3(NTOK, HQ + HKV), 128>>>(qlin, klin, vlin, cosb, sinb,
                                                  qw, kw, qr, kr, vr);
    // scores -> weights region (causal block skip)
    scores_mma<<<dim3(SS / 128, SS / 128, NBH), blk>>>(qr, kr, wptr);
    // in-place causal softmax
    softmax_kernel<<<(unsigned)(NBH * SS), blk>>>(wptr);
    // AV (causal K bound)
    av_mma<<<dim3(1, SS / 128, NBH), blk>>>(wptr, vr, osc);
    // output projection
    gemm_nt_mma<<<dim3(DD / 128, NTOK / 128), blk>>>(osc, Wo, out, HQ * HD, HQ * HD, HQ * HD, DD);
}

// round 5
// speedup vs baseline: 3.3342x; 1.0874x over previous
#include <cuda_runtime.h>
#include <cstdint>

#define BB   2
#define SS   2048
#define DD   1024
#define HQ   16
#define HKV  8
#define HD   128
#define NTOK (BB*SS)     /* 4096 */
#define NBH  (BB*HQ)     /* 32   */

// ---------------- device scratch (static globals; no runtime allocation) ----
__device__ float g_qlin[(size_t)NTOK * HQ  * HD];
__device__ float g_klin[(size_t)NTOK * HKV * HD];
__device__ float g_vlin[(size_t)NTOK * HKV * HD];
__device__ float g_q  [(size_t)BB * HQ  * SS * HD];
__device__ float g_k  [(size_t)BB * HKV * SS * HD];
__device__ float g_v  [(size_t)BB * HKV * SS * HD];
__device__ float g_o  [(size_t)NTOK * HQ * HD];
__device__ float g_wfall[(size_t)BB * HQ * SS * SS];
// tf32-prerounded copies of raw inputs
__device__ float g_hst[(size_t)NTOK * DD];
__device__ float g_wqt[(size_t)HQ  * HD * DD];
__device__ float g_wkt[(size_t)HKV * HD * DD];
__device__ float g_wvt[(size_t)HKV * HD * DD];
__device__ float g_wot[(size_t)DD * HQ * HD];

// ---------------------------------------------------------------------------
__device__ __forceinline__ uint32_t f2tf32(float x) {
    uint32_t r; asm("cvt.rna.tf32.f32 %0, %1;" : "=r"(r) : "f"(x)); return r;
}
__device__ __forceinline__ float rtf(float x) { return __uint_as_float(f2tf32(x)); }
__device__ __forceinline__ void mma8(float* d, const uint32_t* a, const uint32_t* b) {
    asm volatile("mma.sync.aligned.m16n8k8.row.col.f32.tf32.tf32.f32 "
        "{%0,%1,%2,%3}, {%4,%5,%6,%7}, {%8,%9}, {%0,%1,%2,%3};"
        : "+f"(d[0]), "+f"(d[1]), "+f"(d[2]), "+f"(d[3])
        : "r"(a[0]), "r"(a[1]), "r"(a[2]), "r"(a[3]), "r"(b[0]), "r"(b[1]));
}

// 128x128 block tile, 128 threads (4 warps 2x2), warp tile 64x64.
// Inputs MUST be pre-rounded to tf32 values (low mantissa bits zero) so the
// producer path is pure LDG+STS (no cvt). Double-buffered smem, 1 barrier/iter.
// A: row-major MxK. B: NN==0 -> [n][k] (NT); NN==1 -> [k][n].
template<int NN, int RND>
__device__ __forceinline__ void gemm_core(
    const float* __restrict__ A, const float* __restrict__ B,
    float* __restrict__ C, int lda, int ldb, int ldc,
    int kIters, float alpha)
{
    __shared__ uint32_t AsH[2][2][8][32][4];   // [stage][kt][mfrag][lane][reg]
    __shared__ uint32_t BsH[2][2][16][32][2];  // [stage][kt][nfrag][lane][reg]

    const int t = threadIdx.x;
    const int lane = t & 31;
    const int warp = t >> 5;
    const int wm = warp >> 1;   // 0..1
    const int wn = warp & 1;    // 0..1

    float acc[4][8][4];
#pragma unroll
    for (int i = 0; i < 4; i++)
#pragma unroll
        for (int j = 0; j < 8; j++)
#pragma unroll
            for (int r = 0; r < 4; r++) acc[i][j][r] = 0.f;

    // A loader: thread -> rows ra, ra+64; k-group kg
    const int ra = t >> 1, kg = t & 1;
    const float* Ap0 = A + (size_t)ra * lda + kg * 4;
    const float* Ap1 = Ap0 + (size_t)64 * lda;
    const int a_mf   = ra >> 4;              // + 4 for second row
    const int a_ln   = (ra & 7) * 4;
    const int a_rg   = kg * 2 + ((ra >> 3) & 1);

    // B loader
    const float* Bp0 = nullptr; const float* Bp1 = nullptr; const float* BpN = nullptr;
    int b_kt = 0, b_q = 0, b_ch = 0, b_n0 = 0, b_nf = 0, b_lb = 0;
    if (NN) {
        const int kB = t & 15;
        b_n0 = (t >> 4) * 4;                 // + h*32
        BpN  = B + (size_t)kB * ldb + b_n0;
        b_kt = kB >> 3; b_q = kB & 3; b_ch = (kB >> 2) & 1;
    } else {
        const int nb = t >> 1;               // rows nb, nb+64
        Bp0 = B + (size_t)nb * ldb + kg * 4;
        Bp1 = Bp0 + (size_t)64 * ldb;
        b_nf = nb >> 3; b_lb = (nb & 7) * 4;
    }

    float ax[16], bx[16];
    // preload iter 0
    {
        float4 v;
        v = *(const float4*)(Ap0);     ax[0]=v.x; ax[1]=v.y; ax[2]=v.z; ax[3]=v.w;
        v = *(const float4*)(Ap0 + 8); ax[4]=v.x; ax[5]=v.y; ax[6]=v.z; ax[7]=v.w;
        v = *(const float4*)(Ap1);     ax[8]=v.x; ax[9]=v.y; ax[10]=v.z; ax[11]=v.w;
        v = *(const float4*)(Ap1 + 8); ax[12]=v.x; ax[13]=v.y; ax[14]=v.z; ax[15]=v.w;
        if (NN) {
#pragma unroll
            for (int h = 0; h < 4; h++) {
                v = *(const float4*)(BpN + h * 32);
                bx[h*4+0]=v.x; bx[h*4+1]=v.y; bx[h*4+2]=v.z; bx[h*4+3]=v.w;
            }
        } else {
            v = *(const float4*)(Bp0);     bx[0]=v.x; bx[1]=v.y; bx[2]=v.z; bx[3]=v.w;
            v = *(const float4*)(Bp0 + 8); bx[4]=v.x; bx[5]=v.y; bx[6]=v.z; bx[7]=v.w;
            v = *(const float4*)(Bp1);     bx[8]=v.x; bx[9]=v.y; bx[10]=v.z; bx[11]=v.w;
            v = *(const float4*)(Bp1 + 8); bx[12]=v.x; bx[13]=v.y; bx[14]=v.z; bx[15]=v.w;
        }
    }

    for (int it = 0; it < kIters; ++it) {
        const int st = it & 1;
        // scatter A (two rows, both k8 sub-tiles); raw bits, no cvt
#pragma unroll
        for (int rr = 0; rr < 2; rr++) {
            const int mf = a_mf + rr * 4;
#pragma unroll
            for (int kt = 0; kt < 2; kt++)
#pragma unroll
                for (int j = 0; j < 4; j++)
                    AsH[st][kt][mf][a_ln + j][a_rg] = __float_as_uint(ax[rr*8 + kt*4 + j]);
        }
        // scatter B
        if (NN) {
#pragma unroll
            for (int h = 0; h < 4; h++)
#pragma unroll
                for (int j = 0; j < 4; j++) {
                    int nj = b_n0 + h * 32 + j;
                    BsH[st][b_kt][nj >> 3][(nj & 7) * 4 + b_q][b_ch] = __float_as_uint(bx[h*4 + j]);
                }
        } else {
#pragma unroll
            for (int rr = 0; rr < 2; rr++) {
                const int nf = b_nf + rr * 8;
#pragma unroll
                for (int kt = 0; kt < 2; kt++)
#pragma unroll
                    for (int j = 0; j < 4; j++)
                        BsH[st][kt][nf][b_lb + j][kg] = __float_as_uint(bx[rr*8 + kt*4 + j]);
            }
        }
        __syncthreads();
        // preload next iter
        if (it + 1 < kIters) {
            const int k0 = (it + 1) * 16;
            float4 v;
            v = *(const float4*)(Ap0 + k0);     ax[0]=v.x; ax[1]=v.y; ax[2]=v.z; ax[3]=v.w;
            v = *(const float4*)(Ap0 + k0 + 8); ax[4]=v.x; ax[5]=v.y; ax[6]=v.z; ax[7]=v.w;
            v = *(const float4*)(Ap1 + k0);     ax[8]=v.x; ax[9]=v.y; ax[10]=v.z; ax[11]=v.w;
            v = *(const float4*)(Ap1 + k0 + 8); ax[12]=v.x; ax[13]=v.y; ax[14]=v.z; ax[15]=v.w;
            if (NN) {
#pragma unroll
                for (int h = 0; h < 4; h++) {
                    v = *(const float4*)(BpN + (size_t)k0 * ldb + h * 32);
                    bx[h*4+0]=v.x; bx[h*4+1]=v.y; bx[h*4+2]=v.z; bx[h*4+3]=v.w;
                }
            } else {
                v = *(const float4*)(Bp0 + k0);     bx[0]=v.x; bx[1]=v.y; bx[2]=v.z; bx[3]=v.w;
                v = *(const float4*)(Bp0 + k0 + 8); bx[4]=v.x; bx[5]=v.y; bx[6]=v.z; bx[7]=v.w;
                v = *(const float4*)(Bp1 + k0);     bx[8]=v.x; bx[9]=v.y; bx[10]=v.z; bx[11]=v.w;
                v = *(const float4*)(Bp1 + k0 + 8); bx[12]=v.x; bx[13]=v.y; bx[14]=v.z; bx[15]=v.w;
            }
        }
        // compute both k8 sub-tiles
#pragma unroll
        for (int kt = 0; kt < 2; kt++) {
            uint32_t ah[4][4];
#pragma unroll
            for (int i = 0; i < 4; i++) {
                uint4 h = *(const uint4*)&AsH[st][kt][wm * 4 + i][lane][0];
                ah[i][0] = h.x; ah[i][1] = h.y; ah[i][2] = h.z; ah[i][3] = h.w;
            }
            uint32_t bh[8][2];
#pragma unroll
            for (int j = 0; j < 8; j++) {
                uint2 h = *(const uint2*)&BsH[st][kt][wn * 8 + j][lane][0];
                bh[j][0] = h.x; bh[j][1] = h.y;
            }
#pragma unroll
            for (int i = 0; i < 4; i++)
#pragma unroll
                for (int j = 0; j < 8; j++)
                    mma8(acc[i][j], ah[i], bh[j]);
        }
    }
    // epilogue
    const int g = lane >> 2, q = lane & 3;
#pragma unroll
    for (int i = 0; i < 4; i++) {
        int r0 = wm * 64 + i * 16 + g;
#pragma unroll
        for (int j = 0; j < 8; j++) {
            int col = wn * 64 + j * 8 + q * 2;
            float o0 = acc[i][j][0] * alpha, o1 = acc[i][j][1] * alpha;
            float o2 = acc[i][j][2] * alpha, o3 = acc[i][j][3] * alpha;
            if (RND) { o0 = rtf(o0); o1 = rtf(o1); o2 = rtf(o2); o3 = rtf(o3); }
            *(float2*)&C[(size_t)r0 * ldc + col]       = make_float2(o0, o1);
            *(float2*)&C[(size_t)(r0 + 8) * ldc + col] = make_float2(o2, o3);
        }
    }
}

// ---------------- kernel wrappers ------------------------------------------
__global__ void __launch_bounds__(128, 2) qkv_mma(
    const float* __restrict__ hs,
    const float* __restrict__ wq, const float* __restrict__ wk,
    const float* __restrict__ wv,
    float* __restrict__ qlin, float* __restrict__ klin, float* __restrict__ vlin)
{
    const int z = blockIdx.z;
    const int nblk = (z == 0) ? 16 : 8;
    if ((int)blockIdx.x >= nblk) return;
    const float* B = (z == 0) ? wq : ((z == 1) ? wk : wv);
    float* C       = (z == 0) ? qlin : ((z == 1) ? klin : vlin);
    const int ldc  = nblk * 128;
    gemm_core<0,0>(hs + (size_t)blockIdx.y * 128 * DD,
                   B  + (size_t)blockIdx.x * 128 * DD,
                   C  + (size_t)blockIdx.y * 128 * ldc + blockIdx.x * 128,
                   DD, DD, ldc, DD / 16, 1.f);
}

__global__ void __launch_bounds__(128, 2) wo_mma(
    const float* __restrict__ A, const float* __restrict__ B,
    float* __restrict__ C)
{
    gemm_core<0,0>(A + (size_t)blockIdx.y * 128 * (HQ * HD),
                   B + (size_t)blockIdx.x * 128 * (HQ * HD),
                   C + (size_t)blockIdx.y * 128 * DD + blockIdx.x * 128,
                   HQ * HD, HQ * HD, DD, (HQ * HD) / 16, 1.f);
}

__global__ void __launch_bounds__(128, 2) scores_mma(
    const float* __restrict__ Q, const float* __restrict__ Kk,
    float* __restrict__ W)
{
    const int bx = blockIdx.x, by = blockIdx.y, z = blockIdx.z;
    if (bx > by) return;
    const int kvz = (z >> 4) * HKV + ((z & 15) >> 1);
    gemm_core<0,0>(Q  + ((size_t)z   * SS + by * 128) * HD,
                   Kk + ((size_t)kvz * SS + bx * 128) * HD,
                   W + (size_t)z * SS * SS + (size_t)by * 128 * SS + bx * 128,
                   HD, HD, SS, HD / 16, 0.08838834764831845f);
}

__global__ void __launch_bounds__(128, 2) av_mma(
    const float* __restrict__ W, const float* __restrict__ V,
    float* __restrict__ O)
{
    const int my = blockIdx.y, z = blockIdx.z;
    const int kvz = (z >> 4) * HKV + ((z & 15) >> 1);
    const int kIters = (my + 1) * 8;     // causal K bound
    gemm_core<1,1>(W + (size_t)z * SS * SS + (size_t)my * 128 * SS,
                   V + (size_t)kvz * SS * HD,
                   O + (size_t)(z >> 4) * SS * (HQ * HD)
                     + (size_t)my * 128 * (HQ * HD) + (z & 15) * HD,
                   SS, HD, HQ * HD, kIters, 1.f);
}

// ============== tf32 pre-rounding of raw inputs (float4 grid-stride) ========
__global__ void round_kernel(const float* __restrict__ src,
                             float* __restrict__ dst, int n4)
{
    int i = blockIdx.x * 256 + threadIdx.x;
    if (i >= n4) return;
    float4 v = ((const float4*)src)[i];
    v.x = rtf(v.x); v.y = rtf(v.y); v.z = rtf(v.z); v.w = rtf(v.w);
    ((float4*)dst)[i] = v;
}

// ======== RMSNorm + RoPE (+ V relayout), tf32-rounded outputs ===============
__global__ void rmsrope_kernel(const float* __restrict__ qlin,
                               const float* __restrict__ klin,
                               const float* __restrict__ vlin,
                               const float* __restrict__ cosb,
                               const float* __restrict__ sinb,
                               const float* __restrict__ qw,
                               const float* __restrict__ kw,
                               float* __restrict__ qout,
                               float* __restrict__ kout,
                               float* __restrict__ vout)
{
    const int token = blockIdx.x;
    const int y     = blockIdx.y;
    const int i     = threadIdx.x;
    const int b = token >> 11, s = token & (SS - 1);
    __shared__ float sh[128];
    __shared__ float red[4];

    float c  = cosb[(size_t)token * HD + i];
    float sn = sinb[(size_t)token * HD + i];
    float x, w;
    float* outp;
    if (y < HQ) {
        x = qlin[(size_t)token * (HQ * HD) + y * HD + i];
        w = qw[i];
        outp = qout + (((size_t)(b * HQ + y)) * SS + s) * HD;
    } else {
        int h = y - HQ;
        x = klin[(size_t)token * (HKV * HD) + h * HD + i];
        w = kw[i];
        outp = kout + (((size_t)(b * HKV + h)) * SS + s) * HD;
        vout[(((size_t)(b * HKV + h)) * SS + s) * HD + i] =
            rtf(vlin[(size_t)token * (HKV * HD) + h * HD + i]);
    }
    float ss = x * x;
#pragma unroll
    for (int off = 16; off; off >>= 1) ss += __shfl_xor_sync(0xffffffffu, ss, off);
    const int lane = i & 31, wid = i >> 5;
    if (lane == 0) red[wid] = ss;
    __syncthreads();
    ss = red[0] + red[1] + red[2] + red[3];
    float inv = rsqrtf(ss * (1.f / HD) + 1e-6f);
    float xn  = x * inv * w;
    sh[i] = xn;
    __syncthreads();
    float rot = (i < 64) ? -sh[i + 64] : sh[i - 64];
    outp[i] = rtf(xn * c + rot * sn);
}

// ======= in-place causal softmax, tf32-rounded output =======================
__global__ void softmax_kernel(float* __restrict__ W)
{
    const size_t row = blockIdx.x;
    const int iq = (int)(row & (SS - 1));
    float* p = W + row * SS;
    const int L = iq + 1;
    const int t = threadIdx.x;
    __shared__ float red[8];

    float v[8];
#pragma unroll
    for (int r = 0; r < 8; r++) {
        int j = t + r * 256;
        v[r] = (j < L) ? p[j] : 0.f;
    }

    float m = -3.4e38f;
#pragma unroll
    for (int r = 0; r < 8; r++)
        if (t + r * 256 < L) m = fmaxf(m, v[r]);
#pragma unroll
    for (int off = 16; off; off >>= 1) m = fmaxf(m, __shfl_xor_sync(0xffffffffu, m, off));
    if ((t & 31) == 0) red[t >> 5] = m;
    __syncthreads();
    m = red[0];
#pragma unroll
    for (int wq = 1; wq < 8; wq++) m = fmaxf(m, red[wq]);
    __syncthreads();

    float ssum = 0.f;
#pragma unroll
    for (int r = 0; r < 8; r++) {
        int j = t + r * 256;
        float e = (j < L) ? __expf(v[r] - m) : 0.f;
        v[r] = e;
        ssum += e;
    }
#pragma unroll
    for (int off = 16; off; off >>= 1) ssum += __shfl_xor_sync(0xffffffffu, ssum, off);
    if ((t & 31) == 0) red[t >> 5] = ssum;
    __syncthreads();
    ssum = red[0] + red[1] + red[2] + red[3] + red[4] + red[5] + red[6] + red[7];
    const float inv = 1.f / ssum;

#pragma unroll
    for (int r = 0; r < 8; r++) p[t + r * 256] = rtf(v[r] * inv);
}

// ============================== launch ======================================
extern "C" void kernel_launch(void* const* d_in, const int* in_sizes, int n_in,
                              void* d_out, int out_size)
{
    const float* hs   = (const float*)d_in[0];
    const float* cosb = (const float*)d_in[1];
    const float* sinb = (const float*)d_in[2];
    const float* Wq   = (const float*)d_in[4];
    const float* Wk   = (const float*)d_in[5];
    const float* Wv   = (const float*)d_in[6];
    const float* Wo   = (const float*)d_in[7];
    const float* qw   = (const float*)d_in[8];
    const float* kw   = (const float*)d_in[9];
    float* out = (float*)d_out;

    float *qlin, *klin, *vlin, *qr, *kr, *vr, *osc, *wfall;
    float *hst, *wqt, *wkt, *wvt, *wot;
    cudaGetSymbolAddress((void**)&qlin, g_qlin);
    cudaGetSymbolAddress((void**)&klin, g_klin);
    cudaGetSymbolAddress((void**)&vlin, g_vlin);
    cudaGetSymbolAddress((void**)&qr,   g_q);
    cudaGetSymbolAddress((void**)&kr,   g_k);
    cudaGetSymbolAddress((void**)&vr,   g_v);
    cudaGetSymbolAddress((void**)&osc,  g_o);
    cudaGetSymbolAddress((void**)&wfall, g_wfall);
    cudaGetSymbolAddress((void**)&hst,  g_hst);
    cudaGetSymbolAddress((void**)&wqt,  g_wqt);
    cudaGetSymbolAddress((void**)&wkt,  g_wkt);
    cudaGetSymbolAddress((void**)&wvt,  g_wvt);
    cudaGetSymbolAddress((void**)&wot,  g_wot);

    const size_t OUT_ELEMS = (size_t)NTOK * DD;
    const size_t W_ELEMS   = (size_t)BB * HQ * SS * SS;
    float* wptr = ((size_t)out_size >= OUT_ELEMS + W_ELEMS) ? (out + OUT_ELEMS)
                                                            : wfall;

    // tf32 pre-rounding of raw GEMM inputs
    {
        int n;
        n = NTOK * DD / 4;        round_kernel<<<(n + 255) / 256, 256>>>(hs, hst, n);
        n = HQ * HD * DD / 4;     round_kernel<<<(n + 255) / 256, 256>>>(Wq, wqt, n);
        n = HKV * HD * DD / 4;    round_kernel<<<(n + 255) / 256, 256>>>(Wk, wkt, n);
        n = HKV * HD * DD / 4;    round_kernel<<<(n + 255) / 256, 256>>>(Wv, wvt, n);
        n = DD * HQ * HD / 4;     round_kernel<<<(n + 255) / 256, 256>>>(Wo, wot, n);
    }

    dim3 blk(128);
    // QKV projections (one merged launch)
    qkv_mma<<<dim3(16, NTOK / 128, 3), blk>>>(hst, wqt, wkt, wvt, qlin, klin, vlin);
    // RMSNorm + RoPE + V relayout (outputs tf32-rounded)
    rmsrope_kernel<<<dim3(NTOK, HQ + HKV), 128>>>(qlin, klin, vlin, cosb, sinb,
                                                  qw, kw, qr, kr, vr);
    // scores -> weights region (causal block skip)
    scores_mma<<<dim3(SS / 128, SS / 128, NBH), blk>>>(qr, kr, wptr);
    // in-place causal softmax (output tf32-rounded)
    softmax_kernel<<<(unsigned)(NBH * SS), 256>>>(wptr);
    // AV (causal K bound; output tf32-rounded for Wo GEMM)
    av_mma<<<dim3(1, SS / 128, NBH), blk>>>(wptr, vr, osc);
    // output projection
    wo_mma<<<dim3(DD / 128, NTOK / 128), blk>>>(osc, wot, out);
}

// round 10
// speedup vs baseline: 3.3806x; 1.0139x over previous
#include <cuda_runtime.h>
#include <cstdint>

#define BB   2
#define SS   2048
#define DD   1024
#define HQ   16
#define HKV  8
#define HD   128
#define NTOK (BB*SS)
#define NBH  (BB*HQ)

// ---------------- device scratch ------------------------------------------
__device__ float g_qlin[(size_t)NTOK * HQ  * HD];
__device__ float g_klin[(size_t)NTOK * HKV * HD];
__device__ float g_vlin[(size_t)NTOK * HKV * HD];
__device__ float g_q  [(size_t)BB * HQ  * SS * HD];
__device__ float g_k  [(size_t)BB * HKV * SS * HD];
__device__ float g_vt [(size_t)BB * HKV * HD * SS];   // V^T [b][kv][d][s]
__device__ float g_o  [(size_t)NTOK * HQ * HD];
__device__ float g_wfall[(size_t)BB * HQ * SS * SS];
__device__ float g_hst[(size_t)NTOK * DD];
__device__ float g_wqt[(size_t)HQ  * HD * DD];
__device__ float g_wkt[(size_t)HKV * HD * DD];
__device__ float g_wvt[(size_t)HKV * HD * DD];
__device__ float g_wot[(size_t)DD * HQ * HD];

// ---------------------------------------------------------------------------
__device__ __forceinline__ uint32_t f2tf32(float x) {
    uint32_t r; asm("cvt.rna.tf32.f32 %0, %1;" : "=r"(r) : "f"(x)); return r;
}
__device__ __forceinline__ float rtf(float x) { return __uint_as_float(f2tf32(x)); }
__device__ __forceinline__ void mma8(float* d, const uint32_t* a, const uint32_t* b) {
    asm volatile("mma.sync.aligned.m16n8k8.row.col.f32.tf32.tf32.f32 "
        "{%0,%1,%2,%3}, {%4,%5,%6,%7}, {%8,%9}, {%0,%1,%2,%3};"
        : "+f"(d[0]), "+f"(d[1]), "+f"(d[2]), "+f"(d[3])
        : "r"(a[0]), "r"(a[1]), "r"(a[2]), "r"(a[3]), "r"(b[0]), "r"(b[1]));
}

// 128x128 block tile, 128 threads (4 warps 2x2), warp tile 64x64, NT only.
// Inputs must be pre-rounded to tf32 values. Double-buffered smem, vectorized
// STS.128 producers (fragment-ready layout), 1 barrier per k16 iter.
template<int RND>
__device__ __forceinline__ void gemm_core(
    const float* __restrict__ A, const float* __restrict__ B,
    float* __restrict__ C, int lda, int ldb, int ldc,
    int kIters, float alpha)
{
    __shared__ uint32_t AsH[2][2][8][32][4];   // [stage][kt][mfrag][lane][reg]
    __shared__ uint32_t BsH[2][2][16][32][2];  // [stage][kt][nfrag][lane][reg]

    const int t = threadIdx.x;
    const int lane = t & 31;
    const int warp = t >> 5;
    const int wm = warp >> 1;
    const int wn = warp & 1;

    float acc[4][8][4];
#pragma unroll
    for (int i = 0; i < 4; i++)
#pragma unroll
        for (int j = 0; j < 8; j++)
#pragma unroll
            for (int r = 0; r < 4; r++) acc[i][j][r] = 0.f;

    // A producer: pair p = t>>1 covers rows (mf*16+g, +8); ktA = t&1 (k8 half)
    const int pA = t >> 1, ktA = t & 1;
    const int mfA = pA >> 3, gA = pA & 7;
    const float* ApA = A + (size_t)(mfA * 16 + gA) * lda + ktA * 8;
    const float* ApB = ApA + (size_t)8 * lda;
    // B producer: row n = t, both kt
    const float* BpN = B + (size_t)t * ldb;
    const int nfB = t >> 3, lbB = (t & 7) * 4;

    float ax[16];            // x0(0..3) x1(4..7) y0(8..11) y1(12..15)
    float bz[16];            // kt0: z0(0..3) z1(4..7); kt1: (8..15)
    {
        float4 v;
        v = *(const float4*)(ApA);     ax[0]=v.x; ax[1]=v.y; ax[2]=v.z; ax[3]=v.w;
        v = *(const float4*)(ApA + 4); ax[4]=v.x; ax[5]=v.y; ax[6]=v.z; ax[7]=v.w;
        v = *(const float4*)(ApB);     ax[8]=v.x; ax[9]=v.y; ax[10]=v.z; ax[11]=v.w;
        v = *(const float4*)(ApB + 4); ax[12]=v.x; ax[13]=v.y; ax[14]=v.z; ax[15]=v.w;
        v = *(const float4*)(BpN);      bz[0]=v.x; bz[1]=v.y; bz[2]=v.z; bz[3]=v.w;
        v = *(const float4*)(BpN + 4);  bz[4]=v.x; bz[5]=v.y; bz[6]=v.z; bz[7]=v.w;
        v = *(const float4*)(BpN + 8);  bz[8]=v.x; bz[9]=v.y; bz[10]=v.z; bz[11]=v.w;
        v = *(const float4*)(BpN + 12); bz[12]=v.x; bz[13]=v.y; bz[14]=v.z; bz[15]=v.w;
    }

    for (int it = 0; it < kIters; ++it) {
        const int st = it & 1;
        // A: 4 x STS.128, fragment-ready
        {
            uint4* dst = (uint4*)&AsH[st][ktA][mfA][gA * 4][0];
#pragma unroll
            for (int q = 0; q < 4; ++q)
                dst[q] = make_uint4(__float_as_uint(ax[q]),
                                    __float_as_uint(ax[8 + q]),
                                    __float_as_uint(ax[4 + q]),
                                    __float_as_uint(ax[12 + q]));
        }
        // B: 2 kt x 2 STS.128
#pragma unroll
        for (int kt = 0; kt < 2; ++kt) {
            uint4* dst = (uint4*)&BsH[st][kt][nfB][lbB][0];
            const float* z = bz + kt * 8;
            dst[0] = make_uint4(__float_as_uint(z[0]), __float_as_uint(z[4]),
                                __float_as_uint(z[1]), __float_as_uint(z[5]));
            dst[1] = make_uint4(__float_as_uint(z[2]), __float_as_uint(z[6]),
                                __float_as_uint(z[3]), __float_as_uint(z[7]));
        }
        __syncthreads();
        // preload next iter
        if (it + 1 < kIters) {
            const int k0 = (it + 1) * 16;
            float4 v;
            v = *(const float4*)(ApA + k0);     ax[0]=v.x; ax[1]=v.y; ax[2]=v.z; ax[3]=v.w;
            v = *(const float4*)(ApA + k0 + 4); ax[4]=v.x; ax[5]=v.y; ax[6]=v.z; ax[7]=v.w;
            v = *(const float4*)(ApB + k0);     ax[8]=v.x; ax[9]=v.y; ax[10]=v.z; ax[11]=v.w;
            v = *(const float4*)(ApB + k0 + 4); ax[12]=v.x; ax[13]=v.y; ax[14]=v.z; ax[15]=v.w;
            v = *(const float4*)(BpN + k0);      bz[0]=v.x; bz[1]=v.y; bz[2]=v.z; bz[3]=v.w;
            v = *(const float4*)(BpN + k0 + 4);  bz[4]=v.x; bz[5]=v.y; bz[6]=v.z; bz[7]=v.w;
            v = *(const float4*)(BpN + k0 + 8);  bz[8]=v.x; bz[9]=v.y; bz[10]=v.z; bz[11]=v.w;
            v = *(const float4*)(BpN + k0 + 12); bz[12]=v.x; bz[13]=v.y; bz[14]=v.z; bz[15]=v.w;
        }
        // compute both k8 sub-tiles
#pragma unroll
        for (int kt = 0; kt < 2; kt++) {
            uint32_t ah[4][4];
#pragma unroll
            for (int i = 0; i < 4; i++) {
                uint4 h = *(const uint4*)&AsH[st][kt][wm * 4 + i][lane][0];
                ah[i][0] = h.x; ah[i][1] = h.y; ah[i][2] = h.z; ah[i][3] = h.w;
            }
            uint32_t bh[8][2];
#pragma unroll
            for (int j = 0; j < 8; j++) {
                uint2 h = *(const uint2*)&BsH[st][kt][wn * 8 + j][lane][0];
                bh[j][0] = h.x; bh[j][1] = h.y;
            }
#pragma unroll
            for (int i = 0; i < 4; i++)
#pragma unroll
                for (int j = 0; j < 8; j++)
                    mma8(acc[i][j], ah[i], bh[j]);
        }
    }
    // epilogue
    const int g = lane >> 2, q = lane & 3;
#pragma unroll
    for (int i = 0; i < 4; i++) {
        int r0 = wm * 64 + i * 16 + g;
#pragma unroll
        for (int j = 0; j < 8; j++) {
            int col = wn * 64 + j * 8 + q * 2;
            float o0 = acc[i][j][0] * alpha, o1 = acc[i][j][1] * alpha;
            float o2 = acc[i][j][2] * alpha, o3 = acc[i][j][3] * alpha;
            if (RND) { o0 = rtf(o0); o1 = rtf(o1); o2 = rtf(o2); o3 = rtf(o3); }
            *(float2*)&C[(size_t)r0 * ldc + col]       = make_float2(o0, o1);
            *(float2*)&C[(size_t)(r0 + 8) * ldc + col] = make_float2(o2, o3);
        }
    }
}

// ---------------- wrappers -------------------------------------------------
__global__ void __launch_bounds__(128, 2) qkv_mma(
    const float* __restrict__ hs,
    const float* __restrict__ wq, const float* __restrict__ wk,
    const float* __restrict__ wv,
    float* __restrict__ qlin, float* __restrict__ klin, float* __restrict__ vlin)
{
    const int z = blockIdx.z;
    const int nblk = (z == 0) ? 16 : 8;
    if ((int)blockIdx.x >= nblk) return;
    const float* B = (z == 0) ? wq : ((z == 1) ? wk : wv);
    float* C       = (z == 0) ? qlin : ((z == 1) ? klin : vlin);
    const int ldc  = nblk * 128;
    gemm_core<0>(hs + (size_t)blockIdx.y * 128 * DD,
                 B  + (size_t)blockIdx.x * 128 * DD,
                 C  + (size_t)blockIdx.y * 128 * ldc + blockIdx.x * 128,
                 DD, DD, ldc, DD / 16, 1.f);
}

__global__ void __launch_bounds__(128, 2) wo_mma(
    const float* __restrict__ A, const float* __restrict__ B,
    float* __restrict__ C)
{
    gemm_core<0>(A + (size_t)blockIdx.y * 128 * (HQ * HD),
                 B + (size_t)blockIdx.x * 128 * (HQ * HD),
                 C + (size_t)blockIdx.y * 128 * DD + blockIdx.x * 128,
                 HQ * HD, HQ * HD, DD, (HQ * HD) / 16, 1.f);
}

__global__ void __launch_bounds__(128, 2) scores_mma(
    const float* __restrict__ Q, const float* __restrict__ Kk,
    float* __restrict__ W)
{
    const int bx = blockIdx.x, by = blockIdx.y, z = blockIdx.z;
    if (bx > by) return;
    const int kvz = (z >> 4) * HKV + ((z & 15) >> 1);
    gemm_core<0>(Q  + ((size_t)z   * SS + by * 128) * HD,
                 Kk + ((size_t)kvz * SS + bx * 128) * HD,
                 W + (size_t)z * SS * SS + (size_t)by * 128 * SS + bx * 128,
                 HD, HD, SS, HD / 16, 0.08838834764831845f);
}

__global__ void __launch_bounds__(128, 2) av_mma(
    const float* __restrict__ W, const float* __restrict__ Vt,
    float* __restrict__ O)
{
    const int by = blockIdx.y, z = blockIdx.z;
    const int kvz = (z >> 4) * HKV + ((z & 15) >> 1);
    gemm_core<1>(W  + (size_t)z * SS * SS + (size_t)by * 128 * SS,
                 Vt + (size_t)kvz * HD * SS,
                 O + (size_t)(z >> 4) * SS * (HQ * HD)
                   + (size_t)by * 128 * (HQ * HD) + (z & 15) * HD,
                 SS, SS, HQ * HD, (by + 1) * 8, 1.f);
}

// ============== tf32 pre-rounding ==========================================
__global__ void round_kernel(const float* __restrict__ src,
                             float* __restrict__ dst, int n4)
{
    int i = blockIdx.x * 256 + threadIdx.x;
    if (i >= n4) return;
    float4 v = ((const float4*)src)[i];
    v.x = rtf(v.x); v.y = rtf(v.y); v.z = rtf(v.z); v.w = rtf(v.w);
    ((float4*)dst)[i] = v;
}

// ======== RMSNorm + RoPE for Q/K. Grid (NTOK, 24), 128 threads =============
__global__ void rmsrope_kernel(const float* __restrict__ qlin,
                               const float* __restrict__ klin,
                               const float* __restrict__ cosb,
                               const float* __restrict__ sinb,
                               const float* __restrict__ qw,
                               const float* __restrict__ kw,
                               float* __restrict__ qout,
                               float* __restrict__ kout)
{
    const int token = blockIdx.x;
    const int y     = blockIdx.y;
    const int i     = threadIdx.x;
    const int b = token >> 11, s = token & (SS - 1);
    __shared__ float sh[128];
    __shared__ float red[4];

    float c  = cosb[(size_t)token * HD + i];
    float sn = sinb[(size_t)token * HD + i];
    float x, w;
    float* outp;
    if (y < HQ) {
        x = qlin[(size_t)token * (HQ * HD) + y * HD + i];
        w = qw[i];
        outp = qout + (((size_t)(b * HQ + y)) * SS + s) * HD;
    } else {
        int h = y - HQ;
        x = klin[(size_t)token * (HKV * HD) + h * HD + i];
        w = kw[i];
        outp = kout + (((size_t)(b * HKV + h)) * SS + s) * HD;
    }
    float ss = x * x;
#pragma unroll
    for (int off = 16; off; off >>= 1) ss += __shfl_xor_sync(0xffffffffu, ss, off);
    const int lane = i & 31, wd = i >> 5;
    if (lane == 0) red[wd] = ss;
    __syncthreads();
    ss = red[0] + red[1] + red[2] + red[3];
    float inv = rsqrtf(ss * (1.f / HD) + 1e-6f);
    float xn  = x * inv * w;
    sh[i] = xn;
    __syncthreads();
    float rot = (i < 64) ? -sh[i + 64] : sh[i - 64];
    outp[i] = rtf(xn * c + rot * sn);
}

// ======== V transpose: vlin [tok][kv*128] -> vt [b][kv][d][s] ==============
__global__ void vtrans_kernel(const float* __restrict__ vlin,
                              float* __restrict__ vt)
{
    __shared__ float tile[32][33];
    const int bkv = blockIdx.z;
    const int b = bkv >> 3, kv = bkv & 7;
    const int s0 = blockIdx.x * 32, d0 = blockIdx.y * 32;
    const int tx = threadIdx.x, ty = threadIdx.y;   // 32 x 8
#pragma unroll
    for (int r = 0; r < 32; r += 8) {
        int s = s0 + ty + r;
        tile[ty + r][tx] = vlin[((size_t)b * SS + s) * (HKV * HD) + kv * HD + d0 + tx];
    }
    __syncthreads();
#pragma unroll
    for (int r = 0; r < 32; r += 8) {
        int d = d0 + ty + r;
        vt[(((size_t)bkv) * HD + d) * SS + s0 + tx] = rtf(tile[tx][ty + r]);
    }
}

// ======= in-place causal softmax, float4 I/O, tf32-rounded output ==========
__global__ void softmax_kernel(float* __restrict__ W)
{
    const size_t row = blockIdx.x;
    const int iq = (int)(row & (SS - 1));
    const int L = iq + 1;
    float4* p = (float4*)(W + row * SS);
    const int t = threadIdx.x;               // 256 threads, 2 f4 each
    __shared__ float red[8];

    float4 v[2];
    v[0] = p[t]; v[1] = p[t + 256];

    float m = -3.4e38f;
#pragma unroll
    for (int r = 0; r < 2; ++r) {
        int e0 = (t + r * 256) * 4;
        float* f = (float*)&v[r];
#pragma unroll
        for (int e = 0; e < 4; ++e) if (e0 + e < L) m = fmaxf(m, f[e]);
    }
#pragma unroll
    for (int off = 16; off; off >>= 1) m = fmaxf(m, __shfl_xor_sync(0xffffffffu, m, off));
    if ((t & 31) == 0) red[t >> 5] = m;
    __syncthreads();
    m = red[0];
#pragma unroll
    for (int wq = 1; wq < 8; wq++) m = fmaxf(m, red[wq]);
    __syncthreads();

    float ssum = 0.f;
#pragma unroll
    for (int r = 0; r < 2; ++r) {
        int e0 = (t + r * 256) * 4;
        float* f = (float*)&v[r];
#pragma unroll
        for (int e = 0; e < 4; ++e) {
            float ex = (e0 + e < L) ? __expf(f[e] - m) : 0.f;
            f[e] = ex;
            ssum += ex;
        }
    }
#pragma unroll
    for (int off = 16; off; off >>= 1) ssum += __shfl_xor_sync(0xffffffffu, ssum, off);
    if ((t & 31) == 0) red[t >> 5] = ssum;
    __syncthreads();
    ssum = red[0] + red[1] + red[2] + red[3] + red[4] + red[5] + red[6] + red[7];
    const float inv = 1.f / ssum;

#pragma unroll
    for (int r = 0; r < 2; ++r) {
        float* f = (float*)&v[r];
#pragma unroll
        for (int e = 0; e < 4; ++e) f[e] = rtf(f[e] * inv);
        p[t + r * 256] = v[r];
    }
}

// ============================== launch ======================================
extern "C" void kernel_launch(void* const* d_in, const int* in_sizes, int n_in,
                              void* d_out, int out_size)
{
    const float* hs   = (const float*)d_in[0];
    const float* cosb = (const float*)d_in[1];
    const float* sinb = (const float*)d_in[2];
    const float* Wq   = (const float*)d_in[4];
    const float* Wk   = (const float*)d_in[5];
    const float* Wv   = (const float*)d_in[6];
    const float* Wo   = (const float*)d_in[7];
    const float* qw   = (const float*)d_in[8];
    const float* kw   = (const float*)d_in[9];
    float* out = (float*)d_out;

    float *qlin, *klin, *vlin, *qr, *kr, *vt, *osc, *wfall;
    float *hst, *wqt, *wkt, *wvt, *wot;
    cudaGetSymbolAddress((void**)&qlin, g_qlin);
    cudaGetSymbolAddress((void**)&klin, g_klin);
    cudaGetSymbolAddress((void**)&vlin, g_vlin);
    cudaGetSymbolAddress((void**)&qr,   g_q);
    cudaGetSymbolAddress((void**)&kr,   g_k);
    cudaGetSymbolAddress((void**)&vt,   g_vt);
    cudaGetSymbolAddress((void**)&osc,  g_o);
    cudaGetSymbolAddress((void**)&wfall, g_wfall);
    cudaGetSymbolAddress((void**)&hst,  g_hst);
    cudaGetSymbolAddress((void**)&wqt,  g_wqt);
    cudaGetSymbolAddress((void**)&wkt,  g_wkt);
    cudaGetSymbolAddress((void**)&wvt,  g_wvt);
    cudaGetSymbolAddress((void**)&wot,  g_wot);

    const size_t OUT_ELEMS = (size_t)NTOK * DD;
    const size_t W_ELEMS   = (size_t)BB * HQ * SS * SS;
    float* wptr = ((size_t)out_size >= OUT_ELEMS + W_ELEMS) ? (out + OUT_ELEMS)
                                                            : wfall;

    // tf32 pre-rounding of raw GEMM inputs
    {
        int n;
        n = NTOK * DD / 4;        round_kernel<<<(n + 255) / 256, 256>>>(hs, hst, n);
        n = HQ * HD * DD / 4;     round_kernel<<<(n + 255) / 256, 256>>>(Wq, wqt, n);
        n = HKV * HD * DD / 4;    round_kernel<<<(n + 255) / 256, 256>>>(Wk, wkt, n);
        n = HKV * HD * DD / 4;    round_kernel<<<(n + 255) / 256, 256>>>(Wv, wvt, n);
        n = DD * HQ * HD / 4;     round_kernel<<<(n + 255) / 256, 256>>>(Wo, wot, n);
    }

    dim3 blk(128);
    // QKV projections
    qkv_mma<<<dim3(16, NTOK / 128, 3), blk>>>(hst, wqt, wkt, wvt, qlin, klin, vlin);
    // RMSNorm + RoPE (Q,K)
    rmsrope_kernel<<<dim3(NTOK, HQ + HKV), 128>>>(qlin, klin, cosb, sinb,
                                                  qw, kw, qr, kr);
    // V transpose
    vtrans_kernel<<<dim3(SS / 32, HD / 32, BB * HKV), dim3(32, 8)>>>(vlin, vt);
    // scores (causal block skip)
    scores_mma<<<dim3(SS / 128, SS / 128, NBH), blk>>>(qr, kr, wptr);
    // in-place causal softmax
    softmax_kernel<<<(unsigned)(NBH * SS), 256>>>(wptr);
    // AV (causal K bound, NT with V^T)
    av_mma<<<dim3(1, SS / 128, NBH), blk>>>(wptr, vt, osc);
    // output projection
    wo_mma<<<dim3(DD / 128, NTOK / 128), blk>>>(osc, wot, out);
}